// round 11
// baseline (speedup 1.0000x reference)
#include <cuda_runtime.h>
#include <math.h>

// CustomLoss: Voronoi phase -> 32x32 FFT2 magnitude vs Gaussian-mixture target,
// global-normalized scalar loss. GRID=16, PAD=32, RADIUS=8, SIGMA=1.5, NS=24, B=8192.
//
// R10: R9 minus the float2 transpose-buffer merge (it introduced 2-way bank
// conflicts on both stores and loads). Split sGr/sGi planes, stride 36:
// conflict-free in both passes. Keeps __expf, transposed ex, batch pairing.

#define NS 24
#define NT 256
#define NB 2

__device__ double   g_sumP2 = 0.0;
__device__ double   g_sumT2 = 0.0;
__device__ double   g_sumPT = 0.0;
__device__ int      g_maxQ  = 0;   // float bits of max(P^2) (non-negative)
__device__ int      g_maxT  = 0;   // float bits of max(T)
__device__ unsigned g_count = 0;

__global__ void __launch_bounds__(NT, 6) loss_main(
    const float* __restrict__ output,
    const float* __restrict__ targets,
    float* __restrict__ out)
{
    __shared__ __align__(16) float4 sSeed[NS];    // (-2sx, -2sy, sx^2+sy^2+512, 0)
    __shared__ float2 sCS[NS];                    // (cos 2pi z, sin 2pi z) per seed
    __shared__ __align__(16) float sExT[32][26];  // TRANSPOSED: [c][s], stride 26
    __shared__ __align__(16) float sEy[NS][32];   // exp(-(r - ty)^2 / 4.5)
    __shared__ float2 sTw[32];                    // W_32^k = exp(-2*pi*i*k/32)
    __shared__ float  sGr[32][36];                // row-FFT out (re), conflict-free stride
    __shared__ float  sGi[32][36];                // row-FFT out (im)
    __shared__ double redD[24];

    const int tid  = threadIdx.x;
    const int w    = tid >> 5;
    const int lane = tid & 31;

    // ---- twiddle table (once) ----
    if (tid >= 32 && tid < 64) {
        int k = tid - 32;
        float s, c;
        sincospif(-(float)k * (1.0f / 16.0f), &s, &c);
        sTw[k] = make_float2(c, s);
    }
    __syncthreads();

    // ---- hoisted per-lane twiddles ----
    const int colA = lane & 15;
    float2 Wrow = sTw[colA];
    float2 T8   = (lane & 8) ? sTw[(lane & 7) << 1] : make_float2(1.0f, 0.0f);
    float2 T4r  = (lane & 4) ? sTw[(lane & 3) << 2] : make_float2(1.0f, 0.0f);
    const int l7 = lane & 7;
    const int sc = (w << 2) + (lane >> 3);
    float2 W1 = sTw[l7];
    float2 W2 = sTw[l7 << 1];
    float2 W4 = (lane & 4) ? sTw[(lane & 3) << 2] : make_float2(1.0f, 0.0f);

    // Row-pass tiling: row = 8 + (w&3) + 8*(w>>2) + 4*(lane>>4)
    const int  row = 8 + (w & 3) + ((w >> 2) << 3) + ((lane >> 4) << 2);
    const int  rp  = row - 16;
    const int  rp2 = rp * rp;
    const float fi = (float)(row - 8);
    const float fj = (float)((lane & 8) ? (lane & 7) : ((lane & 7) + 8));

    // Output mapping: k1_m = rbase' + perm[m], perm=[0,2,1,3]; r = k1^16.
    // k2(sc) = 2*brev4(sc&15) + (sc>>4); c = k2^16.
    const int rbase = ((__brev(l7) >> 27) ^ 16);  // 4-aligned
    const int c     = ((((__brev(sc & 15) >> 28)) << 1) + (sc >> 4)) ^ 16;

    const int b = blockIdx.x;

    float aP2 = 0.0f, aT2 = 0.0f, aPT = 0.0f, mQ = 0.0f, mT = 0.0f;

    for (int nb = 0; nb < NB; nb++) {
        const int batch = b * NB + nb;
        const float* op = output  + batch * (NS * 3);
        const float* tp = targets + batch * (NS * 3);

        // ---- fills ----
        if (tid < NS) {
            float sx = op[3 * tid + 0];
            float sy = op[3 * tid + 1];
            float z  = op[3 * tid + 2];
            sSeed[tid] = make_float4(-2.0f * sx, -2.0f * sy,
                                     fmaf(sx, sx, fmaf(sy, sy, 512.0f)), 0.0f);
            float s, cz;
            sincospif(2.0f * z, &s, &cz);
            sCS[tid] = make_float2(cz, s);
        }
        for (int t = tid; t < NS * 32; t += NT) {
            int s = t >> 5, x = t & 31;
            float tx  = tp[3 * s + 0];
            float ty  = tp[3 * s + 1];
            float amp = tp[3 * s + 2];
            float dx = (float)x - tx;
            float dy = (float)x - ty;
            sExT[x][s] = amp * __expf(dx * dx * (-1.0f / 4.5f));
            sEy[s][x]  = __expf(dy * dy * (-1.0f / 4.5f));
        }
        __syncthreads();

        // ---- single Voronoi argmin for this thread's ownable cell ----
        int best = 0x7fffffff;
        #pragma unroll
        for (int s = 0; s < NS; s++) {
            float4 S = sSeed[s];
            float val = fmaf(fi, S.x, fmaf(fj, S.y, S.z));
            best = min(best, (__float_as_int(val) & 0xffffffe0) | s);
        }
        const int L = best & 31;

        // ---- density for cells (row, colA) and (row, colA+16) ----
        float xAr, xAi, xBr, xBi;
        {
            int dA = colA - 16;
            bool inA = (rp2 + dA * dA <= 64);
            float2 csA = sCS[L];
            xAr = inA ? csA.x : 1.0f;
            xAi = inA ? csA.y : 0.0f;

            bool inB = (rp2 + colA * colA <= 64);
            int lblB = (colA <= 7) ? L : 0;
            float2 csB = sCS[lblB];
            xBr = inB ? csB.x : 1.0f;
            xBi = inB ? csB.y : 0.0f;
        }

        // ---- analytic row FFTs for rows 0..7 and 24..31 ----
        {
            float dc = (lane == 0) ? 32.0f : 0.0f;
            sGr[w][lane] = dc;            // rows 0..7
            sGi[w][lane] = 0.0f;
            if (w == 0) {
                float2 cs0 = sCS[0];
                float sg = (lane & 16) ? -1.0f : 1.0f;
                sGr[24][lane] = dc + (cs0.x - 1.0f) * sg;
                sGi[24][lane] = cs0.y * sg;
            } else {
                sGr[24 + w][lane] = dc;   // rows 25..31
                sGi[24 + w][lane] = 0.0f;
            }
        }

        // ---- ROW FFT: register stage h=16, then 4 shuffle stages ----
        float ar = xAr + xBr, ai = xAi + xBi;
        float tr = xAr - xBr, ti = xAi - xBi;
        float br = fmaf(tr, Wrow.x, -ti * Wrow.y);
        float bi = fmaf(tr, Wrow.y,  ti * Wrow.x);

        {   // h=8
            float sg = (lane & 8) ? -1.0f : 1.0f;
            float oar = __shfl_xor_sync(0xffffffffu, ar, 8);
            float oai = __shfl_xor_sync(0xffffffffu, ai, 8);
            float obr = __shfl_xor_sync(0xffffffffu, br, 8);
            float obi = __shfl_xor_sync(0xffffffffu, bi, 8);
            float uar = fmaf(sg, ar, oar), uai = fmaf(sg, ai, oai);
            float ubr = fmaf(sg, br, obr), ubi = fmaf(sg, bi, obi);
            ar = fmaf(uar, T8.x, -uai * T8.y); ai = fmaf(uar, T8.y, uai * T8.x);
            br = fmaf(ubr, T8.x, -ubi * T8.y); bi = fmaf(ubr, T8.y, ubi * T8.x);
        }
        {   // h=4
            float sg = (lane & 4) ? -1.0f : 1.0f;
            float oar = __shfl_xor_sync(0xffffffffu, ar, 4);
            float oai = __shfl_xor_sync(0xffffffffu, ai, 4);
            float obr = __shfl_xor_sync(0xffffffffu, br, 4);
            float obi = __shfl_xor_sync(0xffffffffu, bi, 4);
            float uar = fmaf(sg, ar, oar), uai = fmaf(sg, ai, oai);
            float ubr = fmaf(sg, br, obr), ubi = fmaf(sg, bi, obi);
            ar = fmaf(uar, T4r.x, -uai * T4r.y); ai = fmaf(uar, T4r.y, uai * T4r.x);
            br = fmaf(ubr, T4r.x, -ubi * T4r.y); bi = fmaf(ubr, T4r.y, ubi * T4r.x);
        }
        {   // h=2 swap trick
            float sg = (lane & 2) ? -1.0f : 1.0f;
            bool  sw = (lane & 3) == 3;
            float oar = __shfl_xor_sync(0xffffffffu, ar, 2);
            float oai = __shfl_xor_sync(0xffffffffu, ai, 2);
            float obr = __shfl_xor_sync(0xffffffffu, br, 2);
            float obi = __shfl_xor_sync(0xffffffffu, bi, 2);
            float uar = fmaf(sg, ar, oar), uai = fmaf(sg, ai, oai);
            float ubr = fmaf(sg, br, obr), ubi = fmaf(sg, bi, obi);
            ar = sw ?  uai : uar;  ai = sw ? -uar : uai;
            br = sw ?  ubi : ubr;  bi = sw ? -ubr : ubi;
        }
        {   // h=1 identity
            float sg = (lane & 1) ? -1.0f : 1.0f;
            float oar = __shfl_xor_sync(0xffffffffu, ar, 1);
            float oai = __shfl_xor_sync(0xffffffffu, ai, 1);
            float obr = __shfl_xor_sync(0xffffffffu, br, 1);
            float obi = __shfl_xor_sync(0xffffffffu, bi, 1);
            ar = fmaf(sg, ar, oar); ai = fmaf(sg, ai, oai);
            br = fmaf(sg, br, obr); bi = fmaf(sg, bi, obi);
        }

        // store: a -> col colA, b -> col colA+16; banks 4*row+col all distinct
        sGr[row][colA]      = ar;
        sGi[row][colA]      = ai;
        sGr[row][colA + 16] = br;
        sGi[row][colA + 16] = bi;
        __syncthreads();

        // ---- COLUMN FFT: 8 lanes/column, 4 points/thread ----
        float cr[4], ci[4];
        #pragma unroll
        for (int m = 0; m < 4; m++) {
            int p = l7 + (m << 3);
            cr[m] = sGr[p][sc];     // banks 4*p+sc all distinct -> conflict-free
            ci[m] = sGi[p][sc];
        }
        {   // h=16 (register)
            float t0r = cr[0] - cr[2], t0i = ci[0] - ci[2];
            float t1r = cr[1] - cr[3], t1i = ci[1] - ci[3];
            cr[0] += cr[2]; ci[0] += ci[2];
            cr[1] += cr[3]; ci[1] += ci[3];
            cr[2] = fmaf(t0r, W1.x, -t0i * W1.y);
            ci[2] = fmaf(t0r, W1.y,  t0i * W1.x);
            float p1r = fmaf(t1r, W1.x, -t1i * W1.y);
            float p1i = fmaf(t1r, W1.y,  t1i * W1.x);
            cr[3] =  p1i;
            ci[3] = -p1r;
        }
        {   // h=8 (register)
            float t0r = cr[0] - cr[1], t0i = ci[0] - ci[1];
            cr[0] += cr[1]; ci[0] += ci[1];
            cr[1] = fmaf(t0r, W2.x, -t0i * W2.y);
            ci[1] = fmaf(t0r, W2.y,  t0i * W2.x);
            float t1r = cr[2] - cr[3], t1i = ci[2] - ci[3];
            cr[2] += cr[3]; ci[2] += ci[3];
            cr[3] = fmaf(t1r, W2.x, -t1i * W2.y);
            ci[3] = fmaf(t1r, W2.y,  t1i * W2.x);
        }
        {   // h=4 (shuffle)
            float sg = (lane & 4) ? -1.0f : 1.0f;
            #pragma unroll
            for (int m = 0; m < 4; m++) {
                float o_r = __shfl_xor_sync(0xffffffffu, cr[m], 4);
                float o_i = __shfl_xor_sync(0xffffffffu, ci[m], 4);
                float ur = fmaf(sg, cr[m], o_r);
                float ui = fmaf(sg, ci[m], o_i);
                cr[m] = fmaf(ur, W4.x, -ui * W4.y);
                ci[m] = fmaf(ur, W4.y,  ui * W4.x);
            }
        }
        {   // h=2 swap trick
            float sg = (lane & 2) ? -1.0f : 1.0f;
            bool  sw = (lane & 3) == 3;
            #pragma unroll
            for (int m = 0; m < 4; m++) {
                float o_r = __shfl_xor_sync(0xffffffffu, cr[m], 2);
                float o_i = __shfl_xor_sync(0xffffffffu, ci[m], 2);
                float ur = fmaf(sg, cr[m], o_r);
                float ui = fmaf(sg, ci[m], o_i);
                cr[m] = sw ?  ui : ur;
                ci[m] = sw ? -ur : ui;
            }
        }
        {   // h=1 identity
            float sg = (lane & 1) ? -1.0f : 1.0f;
            #pragma unroll
            for (int m = 0; m < 4; m++) {
                float o_r = __shfl_xor_sync(0xffffffffu, cr[m], 1);
                float o_i = __shfl_xor_sync(0xffffffffu, ci[m], 1);
                cr[m] = fmaf(sg, cr[m], o_r);
                ci[m] = fmaf(sg, ci[m], o_i);
            }
        }

        // ---- magnitude + target + accumulate ----
        {
            float Q[4], P[4], T[4];
            #pragma unroll
            for (int m = 0; m < 4; m++) {
                Q[m] = fmaf(cr[m], cr[m], ci[m] * ci[m]);
                P[m] = sqrtf(Q[m]);
                T[m] = 0.0f;
            }
            const float* exRow = &sExT[c][0];
            #pragma unroll
            for (int s2 = 0; s2 < NS / 2; s2++) {
                float2 ex2 = *reinterpret_cast<const float2*>(&exRow[2 * s2]);
                float4 E0  = *reinterpret_cast<const float4*>(&sEy[2 * s2][rbase]);
                float4 E1  = *reinterpret_cast<const float4*>(&sEy[2 * s2 + 1][rbase]);
                T[0] = fmaf(ex2.x, E0.x, fmaf(ex2.y, E1.x, T[0]));   // r offset 0
                T[1] = fmaf(ex2.x, E0.z, fmaf(ex2.y, E1.z, T[1]));   // r offset 2
                T[2] = fmaf(ex2.x, E0.y, fmaf(ex2.y, E1.y, T[2]));   // r offset 1
                T[3] = fmaf(ex2.x, E0.w, fmaf(ex2.y, E1.w, T[3]));   // r offset 3
            }
            #pragma unroll
            for (int m = 0; m < 4; m++) {
                aP2 += Q[m];
                aT2 = fmaf(T[m], T[m], aT2);
                aPT = fmaf(P[m], T[m], aPT);
                mQ = fmaxf(mQ, Q[m]);
                mT = fmaxf(mT, T[m]);
            }
        }
        __syncthreads();   // before next batch overwrites smem
    }

    // ---- block reduction (once per NB batches) ----
    unsigned ruQ = __reduce_max_sync(0xffffffffu, (unsigned)__float_as_int(mQ));
    unsigned ruT = __reduce_max_sync(0xffffffffu, (unsigned)__float_as_int(mT));
    #pragma unroll
    for (int off = 16; off; off >>= 1) {
        aP2 += __shfl_down_sync(0xffffffffu, aP2, off);
        aT2 += __shfl_down_sync(0xffffffffu, aT2, off);
        aPT += __shfl_down_sync(0xffffffffu, aPT, off);
    }
    __shared__ int redI[16];
    if (lane == 0) {
        redD[w]      = (double)aP2;
        redD[8 + w]  = (double)aT2;
        redD[16 + w] = (double)aPT;
        redI[w]      = (int)ruQ;
        redI[8 + w]  = (int)ruT;
    }
    __syncthreads();
    if (tid == 0) {
        double bP2 = 0.0, bT2 = 0.0, bPT = 0.0;
        int    bMQ = 0, bMT = 0;
        #pragma unroll
        for (int i = 0; i < 8; i++) {
            bP2 += redD[i];
            bT2 += redD[8 + i];
            bPT += redD[16 + i];
            bMQ = max(bMQ, redI[i]);
            bMT = max(bMT, redI[8 + i]);
        }
        atomicAdd(&g_sumP2, bP2);
        atomicAdd(&g_sumT2, bT2);
        atomicAdd(&g_sumPT, bPT);
        atomicMax(&g_maxQ, bMQ);
        atomicMax(&g_maxT, bMT);

        __threadfence();
        unsigned prev = atomicAdd(&g_count, 1u);
        if (prev == gridDim.x - 1u) {
            __threadfence();
            double SP2 = g_sumP2;
            double ST2 = g_sumT2;
            double SPT = g_sumPT;
            double Mp = sqrt((double)__int_as_float(g_maxQ));
            double Mt = (double)__int_as_float(g_maxT);
            double num = SP2 / (Mp * Mp) - 2.0 * SPT / (Mp * Mt) + ST2 / (Mt * Mt);
            out[0] = (float)(num * (Mp * Mt) / sqrt(SP2 * ST2));
            // self-reset for next graph replay (matches static init state)
            g_sumP2 = 0.0;
            g_sumT2 = 0.0;
            g_sumPT = 0.0;
            g_maxQ  = 0;
            g_maxT  = 0;
            g_count = 0u;
        }
    }
}

extern "C" void kernel_launch(void* const* d_in, const int* in_sizes, int n_in,
                              void* d_out, int out_size)
{
    const float* output  = (const float*)d_in[0];
    const float* targets = (const float*)d_in[1];
    int B = in_sizes[0] / (NS * 3);

    loss_main<<<B / NB, NT>>>(output, targets, (float*)d_out);
}

// round 13
// speedup vs baseline: 1.5784x; 1.5784x over previous
#include <cuda_runtime.h>
#include <math.h>

// CustomLoss: Voronoi phase -> 32x32 FFT2 magnitude vs Gaussian-mixture target,
// global-normalized scalar loss. GRID=16, PAD=32, RADIUS=8, SIGMA=1.5, NS=24, B=8192.
//
// R13 (== R10/R12 resubmit; R11 was a throttled container, R12 an infra
// failure — this binary is still unmeasured on healthy hardware):
// split sGr/sGi planes stride 36 (conflict-free both passes), __expf tables,
// transposed ex table, 2 batches/block, fused device-side finalize.

#define NS 24
#define NT 256
#define NB 2

__device__ double   g_sumP2 = 0.0;
__device__ double   g_sumT2 = 0.0;
__device__ double   g_sumPT = 0.0;
__device__ int      g_maxQ  = 0;   // float bits of max(P^2) (non-negative)
__device__ int      g_maxT  = 0;   // float bits of max(T)
__device__ unsigned g_count = 0;

__global__ void __launch_bounds__(NT, 6) loss_main(
    const float* __restrict__ output,
    const float* __restrict__ targets,
    float* __restrict__ out)
{
    __shared__ __align__(16) float4 sSeed[NS];    // (-2sx, -2sy, sx^2+sy^2+512, 0)
    __shared__ float2 sCS[NS];                    // (cos 2pi z, sin 2pi z) per seed
    __shared__ __align__(16) float sExT[32][26];  // TRANSPOSED: [c][s], stride 26
    __shared__ __align__(16) float sEy[NS][32];   // exp(-(r - ty)^2 / 4.5)
    __shared__ float2 sTw[32];                    // W_32^k = exp(-2*pi*i*k/32)
    __shared__ float  sGr[32][36];                // row-FFT out (re), conflict-free stride
    __shared__ float  sGi[32][36];                // row-FFT out (im)
    __shared__ double redD[24];

    const int tid  = threadIdx.x;
    const int w    = tid >> 5;
    const int lane = tid & 31;

    // ---- twiddle table (once) ----
    if (tid >= 32 && tid < 64) {
        int k = tid - 32;
        float s, c;
        sincospif(-(float)k * (1.0f / 16.0f), &s, &c);
        sTw[k] = make_float2(c, s);
    }
    __syncthreads();

    // ---- hoisted per-lane twiddles ----
    const int colA = lane & 15;
    float2 Wrow = sTw[colA];
    float2 T8   = (lane & 8) ? sTw[(lane & 7) << 1] : make_float2(1.0f, 0.0f);
    float2 T4r  = (lane & 4) ? sTw[(lane & 3) << 2] : make_float2(1.0f, 0.0f);
    const int l7 = lane & 7;
    const int sc = (w << 2) + (lane >> 3);
    float2 W1 = sTw[l7];
    float2 W2 = sTw[l7 << 1];
    float2 W4 = (lane & 4) ? sTw[(lane & 3) << 2] : make_float2(1.0f, 0.0f);

    // Row-pass tiling: row = 8 + (w&3) + 8*(w>>2) + 4*(lane>>4)
    const int  row = 8 + (w & 3) + ((w >> 2) << 3) + ((lane >> 4) << 2);
    const int  rp  = row - 16;
    const int  rp2 = rp * rp;
    const float fi = (float)(row - 8);
    const float fj = (float)((lane & 8) ? (lane & 7) : ((lane & 7) + 8));

    // Output mapping: k1_m = rbase' + perm[m], perm=[0,2,1,3]; r = k1^16.
    // k2(sc) = 2*brev4(sc&15) + (sc>>4); c = k2^16.
    const int rbase = ((__brev(l7) >> 27) ^ 16);  // 4-aligned
    const int c     = ((((__brev(sc & 15) >> 28)) << 1) + (sc >> 4)) ^ 16;

    const int b = blockIdx.x;

    float aP2 = 0.0f, aT2 = 0.0f, aPT = 0.0f, mQ = 0.0f, mT = 0.0f;

    for (int nb = 0; nb < NB; nb++) {
        const int batch = b * NB + nb;
        const float* op = output  + batch * (NS * 3);
        const float* tp = targets + batch * (NS * 3);

        // ---- fills ----
        if (tid < NS) {
            float sx = op[3 * tid + 0];
            float sy = op[3 * tid + 1];
            float z  = op[3 * tid + 2];
            sSeed[tid] = make_float4(-2.0f * sx, -2.0f * sy,
                                     fmaf(sx, sx, fmaf(sy, sy, 512.0f)), 0.0f);
            float s, cz;
            sincospif(2.0f * z, &s, &cz);
            sCS[tid] = make_float2(cz, s);
        }
        for (int t = tid; t < NS * 32; t += NT) {
            int s = t >> 5, x = t & 31;
            float tx  = tp[3 * s + 0];
            float ty  = tp[3 * s + 1];
            float amp = tp[3 * s + 2];
            float dx = (float)x - tx;
            float dy = (float)x - ty;
            sExT[x][s] = amp * __expf(dx * dx * (-1.0f / 4.5f));
            sEy[s][x]  = __expf(dy * dy * (-1.0f / 4.5f));
        }
        __syncthreads();

        // ---- single Voronoi argmin for this thread's ownable cell ----
        int best = 0x7fffffff;
        #pragma unroll
        for (int s = 0; s < NS; s++) {
            float4 S = sSeed[s];
            float val = fmaf(fi, S.x, fmaf(fj, S.y, S.z));
            best = min(best, (__float_as_int(val) & 0xffffffe0) | s);
        }
        const int L = best & 31;

        // ---- density for cells (row, colA) and (row, colA+16) ----
        float xAr, xAi, xBr, xBi;
        {
            int dA = colA - 16;
            bool inA = (rp2 + dA * dA <= 64);
            float2 csA = sCS[L];
            xAr = inA ? csA.x : 1.0f;
            xAi = inA ? csA.y : 0.0f;

            bool inB = (rp2 + colA * colA <= 64);
            int lblB = (colA <= 7) ? L : 0;
            float2 csB = sCS[lblB];
            xBr = inB ? csB.x : 1.0f;
            xBi = inB ? csB.y : 0.0f;
        }

        // ---- analytic row FFTs for rows 0..7 and 24..31 ----
        {
            float dc = (lane == 0) ? 32.0f : 0.0f;
            sGr[w][lane] = dc;            // rows 0..7
            sGi[w][lane] = 0.0f;
            if (w == 0) {
                float2 cs0 = sCS[0];
                float sg = (lane & 16) ? -1.0f : 1.0f;
                sGr[24][lane] = dc + (cs0.x - 1.0f) * sg;
                sGi[24][lane] = cs0.y * sg;
            } else {
                sGr[24 + w][lane] = dc;   // rows 25..31
                sGi[24 + w][lane] = 0.0f;
            }
        }

        // ---- ROW FFT: register stage h=16, then 4 shuffle stages ----
        float ar = xAr + xBr, ai = xAi + xBi;
        float tr = xAr - xBr, ti = xAi - xBi;
        float br = fmaf(tr, Wrow.x, -ti * Wrow.y);
        float bi = fmaf(tr, Wrow.y,  ti * Wrow.x);

        {   // h=8
            float sg = (lane & 8) ? -1.0f : 1.0f;
            float oar = __shfl_xor_sync(0xffffffffu, ar, 8);
            float oai = __shfl_xor_sync(0xffffffffu, ai, 8);
            float obr = __shfl_xor_sync(0xffffffffu, br, 8);
            float obi = __shfl_xor_sync(0xffffffffu, bi, 8);
            float uar = fmaf(sg, ar, oar), uai = fmaf(sg, ai, oai);
            float ubr = fmaf(sg, br, obr), ubi = fmaf(sg, bi, obi);
            ar = fmaf(uar, T8.x, -uai * T8.y); ai = fmaf(uar, T8.y, uai * T8.x);
            br = fmaf(ubr, T8.x, -ubi * T8.y); bi = fmaf(ubr, T8.y, ubi * T8.x);
        }
        {   // h=4
            float sg = (lane & 4) ? -1.0f : 1.0f;
            float oar = __shfl_xor_sync(0xffffffffu, ar, 4);
            float oai = __shfl_xor_sync(0xffffffffu, ai, 4);
            float obr = __shfl_xor_sync(0xffffffffu, br, 4);
            float obi = __shfl_xor_sync(0xffffffffu, bi, 4);
            float uar = fmaf(sg, ar, oar), uai = fmaf(sg, ai, oai);
            float ubr = fmaf(sg, br, obr), ubi = fmaf(sg, bi, obi);
            ar = fmaf(uar, T4r.x, -uai * T4r.y); ai = fmaf(uar, T4r.y, uai * T4r.x);
            br = fmaf(ubr, T4r.x, -ubi * T4r.y); bi = fmaf(ubr, T4r.y, ubi * T4r.x);
        }
        {   // h=2 swap trick
            float sg = (lane & 2) ? -1.0f : 1.0f;
            bool  sw = (lane & 3) == 3;
            float oar = __shfl_xor_sync(0xffffffffu, ar, 2);
            float oai = __shfl_xor_sync(0xffffffffu, ai, 2);
            float obr = __shfl_xor_sync(0xffffffffu, br, 2);
            float obi = __shfl_xor_sync(0xffffffffu, bi, 2);
            float uar = fmaf(sg, ar, oar), uai = fmaf(sg, ai, oai);
            float ubr = fmaf(sg, br, obr), ubi = fmaf(sg, bi, obi);
            ar = sw ?  uai : uar;  ai = sw ? -uar : uai;
            br = sw ?  ubi : ubr;  bi = sw ? -ubr : ubi;
        }
        {   // h=1 identity
            float sg = (lane & 1) ? -1.0f : 1.0f;
            float oar = __shfl_xor_sync(0xffffffffu, ar, 1);
            float oai = __shfl_xor_sync(0xffffffffu, ai, 1);
            float obr = __shfl_xor_sync(0xffffffffu, br, 1);
            float obi = __shfl_xor_sync(0xffffffffu, bi, 1);
            ar = fmaf(sg, ar, oar); ai = fmaf(sg, ai, oai);
            br = fmaf(sg, br, obr); bi = fmaf(sg, bi, obi);
        }

        // store: a -> col colA, b -> col colA+16; banks 4*row+col all distinct
        sGr[row][colA]      = ar;
        sGi[row][colA]      = ai;
        sGr[row][colA + 16] = br;
        sGi[row][colA + 16] = bi;
        __syncthreads();

        // ---- COLUMN FFT: 8 lanes/column, 4 points/thread ----
        float cr[4], ci[4];
        #pragma unroll
        for (int m = 0; m < 4; m++) {
            int p = l7 + (m << 3);
            cr[m] = sGr[p][sc];     // banks 4*p+sc all distinct -> conflict-free
            ci[m] = sGi[p][sc];
        }
        {   // h=16 (register)
            float t0r = cr[0] - cr[2], t0i = ci[0] - ci[2];
            float t1r = cr[1] - cr[3], t1i = ci[1] - ci[3];
            cr[0] += cr[2]; ci[0] += ci[2];
            cr[1] += cr[3]; ci[1] += ci[3];
            cr[2] = fmaf(t0r, W1.x, -t0i * W1.y);
            ci[2] = fmaf(t0r, W1.y,  t0i * W1.x);
            float p1r = fmaf(t1r, W1.x, -t1i * W1.y);
            float p1i = fmaf(t1r, W1.y,  t1i * W1.x);
            cr[3] =  p1i;
            ci[3] = -p1r;
        }
        {   // h=8 (register)
            float t0r = cr[0] - cr[1], t0i = ci[0] - ci[1];
            cr[0] += cr[1]; ci[0] += ci[1];
            cr[1] = fmaf(t0r, W2.x, -t0i * W2.y);
            ci[1] = fmaf(t0r, W2.y,  t0i * W2.x);
            float t1r = cr[2] - cr[3], t1i = ci[2] - ci[3];
            cr[2] += cr[3]; ci[2] += ci[3];
            cr[3] = fmaf(t1r, W2.x, -t1i * W2.y);
            ci[3] = fmaf(t1r, W2.y,  t1i * W2.x);
        }
        {   // h=4 (shuffle)
            float sg = (lane & 4) ? -1.0f : 1.0f;
            #pragma unroll
            for (int m = 0; m < 4; m++) {
                float o_r = __shfl_xor_sync(0xffffffffu, cr[m], 4);
                float o_i = __shfl_xor_sync(0xffffffffu, ci[m], 4);
                float ur = fmaf(sg, cr[m], o_r);
                float ui = fmaf(sg, ci[m], o_i);
                cr[m] = fmaf(ur, W4.x, -ui * W4.y);
                ci[m] = fmaf(ur, W4.y,  ui * W4.x);
            }
        }
        {   // h=2 swap trick
            float sg = (lane & 2) ? -1.0f : 1.0f;
            bool  sw = (lane & 3) == 3;
            #pragma unroll
            for (int m = 0; m < 4; m++) {
                float o_r = __shfl_xor_sync(0xffffffffu, cr[m], 2);
                float o_i = __shfl_xor_sync(0xffffffffu, ci[m], 2);
                float ur = fmaf(sg, cr[m], o_r);
                float ui = fmaf(sg, ci[m], o_i);
                cr[m] = sw ?  ui : ur;
                ci[m] = sw ? -ur : ui;
            }
        }
        {   // h=1 identity
            float sg = (lane & 1) ? -1.0f : 1.0f;
            #pragma unroll
            for (int m = 0; m < 4; m++) {
                float o_r = __shfl_xor_sync(0xffffffffu, cr[m], 1);
                float o_i = __shfl_xor_sync(0xffffffffu, ci[m], 1);
                cr[m] = fmaf(sg, cr[m], o_r);
                ci[m] = fmaf(sg, ci[m], o_i);
            }
        }

        // ---- magnitude + target + accumulate ----
        {
            float Q[4], P[4], T[4];
            #pragma unroll
            for (int m = 0; m < 4; m++) {
                Q[m] = fmaf(cr[m], cr[m], ci[m] * ci[m]);
                P[m] = sqrtf(Q[m]);
                T[m] = 0.0f;
            }
            const float* exRow = &sExT[c][0];
            #pragma unroll
            for (int s2 = 0; s2 < NS / 2; s2++) {
                float2 ex2 = *reinterpret_cast<const float2*>(&exRow[2 * s2]);
                float4 E0  = *reinterpret_cast<const float4*>(&sEy[2 * s2][rbase]);
                float4 E1  = *reinterpret_cast<const float4*>(&sEy[2 * s2 + 1][rbase]);
                T[0] = fmaf(ex2.x, E0.x, fmaf(ex2.y, E1.x, T[0]));   // r offset 0
                T[1] = fmaf(ex2.x, E0.z, fmaf(ex2.y, E1.z, T[1]));   // r offset 2
                T[2] = fmaf(ex2.x, E0.y, fmaf(ex2.y, E1.y, T[2]));   // r offset 1
                T[3] = fmaf(ex2.x, E0.w, fmaf(ex2.y, E1.w, T[3]));   // r offset 3
            }
            #pragma unroll
            for (int m = 0; m < 4; m++) {
                aP2 += Q[m];
                aT2 = fmaf(T[m], T[m], aT2);
                aPT = fmaf(P[m], T[m], aPT);
                mQ = fmaxf(mQ, Q[m]);
                mT = fmaxf(mT, T[m]);
            }
        }
        __syncthreads();   // before next batch overwrites smem
    }

    // ---- block reduction (once per NB batches) ----
    unsigned ruQ = __reduce_max_sync(0xffffffffu, (unsigned)__float_as_int(mQ));
    unsigned ruT = __reduce_max_sync(0xffffffffu, (unsigned)__float_as_int(mT));
    #pragma unroll
    for (int off = 16; off; off >>= 1) {
        aP2 += __shfl_down_sync(0xffffffffu, aP2, off);
        aT2 += __shfl_down_sync(0xffffffffu, aT2, off);
        aPT += __shfl_down_sync(0xffffffffu, aPT, off);
    }
    __shared__ int redI[16];
    if (lane == 0) {
        redD[w]      = (double)aP2;
        redD[8 + w]  = (double)aT2;
        redD[16 + w] = (double)aPT;
        redI[w]      = (int)ruQ;
        redI[8 + w]  = (int)ruT;
    }
    __syncthreads();
    if (tid == 0) {
        double bP2 = 0.0, bT2 = 0.0, bPT = 0.0;
        int    bMQ = 0, bMT = 0;
        #pragma unroll
        for (int i = 0; i < 8; i++) {
            bP2 += redD[i];
            bT2 += redD[8 + i];
            bPT += redD[16 + i];
            bMQ = max(bMQ, redI[i]);
            bMT = max(bMT, redI[8 + i]);
        }
        atomicAdd(&g_sumP2, bP2);
        atomicAdd(&g_sumT2, bT2);
        atomicAdd(&g_sumPT, bPT);
        atomicMax(&g_maxQ, bMQ);
        atomicMax(&g_maxT, bMT);

        __threadfence();
        unsigned prev = atomicAdd(&g_count, 1u);
        if (prev == gridDim.x - 1u) {
            __threadfence();
            double SP2 = g_sumP2;
            double ST2 = g_sumT2;
            double SPT = g_sumPT;
            double Mp = sqrt((double)__int_as_float(g_maxQ));
            double Mt = (double)__int_as_float(g_maxT);
            double num = SP2 / (Mp * Mp) - 2.0 * SPT / (Mp * Mt) + ST2 / (Mt * Mt);
            out[0] = (float)(num * (Mp * Mt) / sqrt(SP2 * ST2));
            // self-reset for next graph replay (matches static init state)
            g_sumP2 = 0.0;
            g_sumT2 = 0.0;
            g_sumPT = 0.0;
            g_maxQ  = 0;
            g_maxT  = 0;
            g_count = 0u;
        }
    }
}

extern "C" void kernel_launch(void* const* d_in, const int* in_sizes, int n_in,
                              void* d_out, int out_size)
{
    const float* output  = (const float*)d_in[0];
    const float* targets = (const float*)d_in[1];
    int B = in_sizes[0] / (NS * 3);

    loss_main<<<B / NB, NT>>>(output, targets, (float*)d_out);
}

// round 14
// speedup vs baseline: 1.6288x; 1.0319x over previous
#include <cuda_runtime.h>
#include <math.h>

// CustomLoss: Voronoi phase -> 32x32 FFT2 magnitude vs Gaussian-mixture target,
// global-normalized scalar loss. GRID=16, PAD=32, RADIUS=8, SIGMA=1.5, NS=24, B=8192.
//
// R14 = R9 (best, merged float2 transpose buffer) + sparse column FFT:
// trivial rows never touch smem; their contribution is 1024*delta(DC) plus the
// row-24 term e*(i^k1) added analytically. Column pass loads 2 rows, not 4.

#define NS 24
#define NT 256
#define NB 2

__device__ double   g_sumP2 = 0.0;
__device__ double   g_sumT2 = 0.0;
__device__ double   g_sumPT = 0.0;
__device__ int      g_maxQ  = 0;   // float bits of max(P^2) (non-negative)
__device__ int      g_maxT  = 0;   // float bits of max(T)
__device__ unsigned g_count = 0;

__global__ void __launch_bounds__(NT, 6) loss_main(
    const float* __restrict__ output,
    const float* __restrict__ targets,
    float* __restrict__ out)
{
    __shared__ __align__(16) float4 sSeed[NS];    // (-2sx, -2sy, sx^2+sy^2+512, 0)
    __shared__ float2 sCS[NS];                    // (cos 2pi z, sin 2pi z) per seed
    __shared__ __align__(16) float sExT[32][26];  // TRANSPOSED: [c][s], stride 26
    __shared__ __align__(16) float sEy[NS][32];   // exp(-(r - ty)^2 / 4.5)
    __shared__ float2 sTw[32];                    // W_32^k = exp(-2*pi*i*k/32)
    __shared__ __align__(16) float2 sG[32][36];   // row-FFT out (rows 8..23 only used)
    __shared__ double redD[24];

    const int tid  = threadIdx.x;
    const int w    = tid >> 5;
    const int lane = tid & 31;

    // ---- twiddle table (once) ----
    if (tid >= 32 && tid < 64) {
        int k = tid - 32;
        float s, c;
        sincospif(-(float)k * (1.0f / 16.0f), &s, &c);
        sTw[k] = make_float2(c, s);
    }
    __syncthreads();

    // ---- hoisted per-lane twiddles ----
    const int colA = lane & 15;
    float2 Wrow = sTw[colA];
    float2 T8   = (lane & 8) ? sTw[(lane & 7) << 1] : make_float2(1.0f, 0.0f);
    float2 T4r  = (lane & 4) ? sTw[(lane & 3) << 2] : make_float2(1.0f, 0.0f);
    const int l7 = lane & 7;
    const int sc = (w << 2) + (lane >> 3);
    float2 W1 = sTw[l7];
    float2 W2 = sTw[l7 << 1];
    float2 W4 = (lane & 4) ? sTw[(lane & 3) << 2] : make_float2(1.0f, 0.0f);

    // Row-pass tiling: row = 8 + (w&3) + 8*(w>>2) + 4*(lane>>4)
    const int  row = 8 + (w & 3) + ((w >> 2) << 3) + ((lane >> 4) << 2);
    const int  rp  = row - 16;
    const int  rp2 = rp * rp;
    const float fi = (float)(row - 8);
    const float fj = (float)((lane & 8) ? (lane & 7) : ((lane & 7) + 8));

    // Output mapping: k1_m = brev5(l7+8m); k1 mod 4 = perm[m]=[0,2,1,3]; r = k1^16.
    // k2(sc) = 2*brev4(sc&15) + (sc>>4); c = k2^16; parity(k2) = sc>>4.
    const int rbase = ((__brev(l7) >> 27) ^ 16);  // 4-aligned
    const int c     = ((((__brev(sc & 15) >> 28)) << 1) + (sc >> 4)) ^ 16;
    const float kpar = (sc >= 16) ? -1.0f : 1.0f; // (-1)^{k2}

    const int b = blockIdx.x;

    float aP2 = 0.0f, aT2 = 0.0f, aPT = 0.0f, mQ = 0.0f, mT = 0.0f;

    for (int nb = 0; nb < NB; nb++) {
        const int batch = b * NB + nb;
        const float* op = output  + batch * (NS * 3);
        const float* tp = targets + batch * (NS * 3);

        // ---- fills ----
        if (tid < NS) {
            float sx = op[3 * tid + 0];
            float sy = op[3 * tid + 1];
            float z  = op[3 * tid + 2];
            sSeed[tid] = make_float4(-2.0f * sx, -2.0f * sy,
                                     fmaf(sx, sx, fmaf(sy, sy, 512.0f)), 0.0f);
            float s, cz;
            sincospif(2.0f * z, &s, &cz);
            sCS[tid] = make_float2(cz, s);
        }
        for (int t = tid; t < NS * 32; t += NT) {
            int s = t >> 5, x = t & 31;
            float tx  = tp[3 * s + 0];
            float ty  = tp[3 * s + 1];
            float amp = tp[3 * s + 2];
            float dx = (float)x - tx;
            float dy = (float)x - ty;
            sExT[x][s] = amp * __expf(dx * dx * (-1.0f / 4.5f));
            sEy[s][x]  = __expf(dy * dy * (-1.0f / 4.5f));
        }
        __syncthreads();

        // ---- single Voronoi argmin for this thread's ownable cell ----
        int best = 0x7fffffff;
        #pragma unroll
        for (int s = 0; s < NS; s++) {
            float4 S = sSeed[s];
            float val = fmaf(fi, S.x, fmaf(fj, S.y, S.z));
            best = min(best, (__float_as_int(val) & 0xffffffe0) | s);
        }
        const int L = best & 31;

        // ---- density for cells (row, colA) and (row, colA+16) ----
        float xAr, xAi, xBr, xBi;
        {
            int dA = colA - 16;
            bool inA = (rp2 + dA * dA <= 64);
            float2 csA = sCS[L];
            xAr = inA ? csA.x : 1.0f;
            xAi = inA ? csA.y : 0.0f;

            bool inB = (rp2 + colA * colA <= 64);
            int lblB = (colA <= 7) ? L : 0;
            float2 csB = sCS[lblB];
            xBr = inB ? csB.x : 1.0f;
            xBi = inB ? csB.y : 0.0f;
        }

        // ---- ROW FFT: register stage h=16, then 4 shuffle stages ----
        float ar = xAr + xBr, ai = xAi + xBi;
        float tr = xAr - xBr, ti = xAi - xBi;
        float br = fmaf(tr, Wrow.x, -ti * Wrow.y);
        float bi = fmaf(tr, Wrow.y,  ti * Wrow.x);

        {   // h=8
            float sg = (lane & 8) ? -1.0f : 1.0f;
            float oar = __shfl_xor_sync(0xffffffffu, ar, 8);
            float oai = __shfl_xor_sync(0xffffffffu, ai, 8);
            float obr = __shfl_xor_sync(0xffffffffu, br, 8);
            float obi = __shfl_xor_sync(0xffffffffu, bi, 8);
            float uar = fmaf(sg, ar, oar), uai = fmaf(sg, ai, oai);
            float ubr = fmaf(sg, br, obr), ubi = fmaf(sg, bi, obi);
            ar = fmaf(uar, T8.x, -uai * T8.y); ai = fmaf(uar, T8.y, uai * T8.x);
            br = fmaf(ubr, T8.x, -ubi * T8.y); bi = fmaf(ubr, T8.y, ubi * T8.x);
        }
        {   // h=4
            float sg = (lane & 4) ? -1.0f : 1.0f;
            float oar = __shfl_xor_sync(0xffffffffu, ar, 4);
            float oai = __shfl_xor_sync(0xffffffffu, ai, 4);
            float obr = __shfl_xor_sync(0xffffffffu, br, 4);
            float obi = __shfl_xor_sync(0xffffffffu, bi, 4);
            float uar = fmaf(sg, ar, oar), uai = fmaf(sg, ai, oai);
            float ubr = fmaf(sg, br, obr), ubi = fmaf(sg, bi, obi);
            ar = fmaf(uar, T4r.x, -uai * T4r.y); ai = fmaf(uar, T4r.y, uai * T4r.x);
            br = fmaf(ubr, T4r.x, -ubi * T4r.y); bi = fmaf(ubr, T4r.y, ubi * T4r.x);
        }
        {   // h=2 swap trick
            float sg = (lane & 2) ? -1.0f : 1.0f;
            bool  sw = (lane & 3) == 3;
            float oar = __shfl_xor_sync(0xffffffffu, ar, 2);
            float oai = __shfl_xor_sync(0xffffffffu, ai, 2);
            float obr = __shfl_xor_sync(0xffffffffu, br, 2);
            float obi = __shfl_xor_sync(0xffffffffu, bi, 2);
            float uar = fmaf(sg, ar, oar), uai = fmaf(sg, ai, oai);
            float ubr = fmaf(sg, br, obr), ubi = fmaf(sg, bi, obi);
            ar = sw ?  uai : uar;  ai = sw ? -uar : uai;
            br = sw ?  ubi : ubr;  bi = sw ? -ubr : ubi;
        }
        {   // h=1 identity
            float sg = (lane & 1) ? -1.0f : 1.0f;
            float oar = __shfl_xor_sync(0xffffffffu, ar, 1);
            float oai = __shfl_xor_sync(0xffffffffu, ai, 1);
            float obr = __shfl_xor_sync(0xffffffffu, br, 1);
            float obi = __shfl_xor_sync(0xffffffffu, bi, 1);
            ar = fmaf(sg, ar, oar); ai = fmaf(sg, ai, oai);
            br = fmaf(sg, br, obr); bi = fmaf(sg, bi, obi);
        }

        // DC-bin adjustment: storage col 0 holds k2=0; Ghat = G - 32 there.
        if (colA == 0) ar -= 32.0f;

        // store: a -> col colA, b -> col colA+16 (rows 8..23 only)
        sG[row][colA]      = make_float2(ar, ai);
        sG[row][colA + 16] = make_float2(br, bi);
        __syncthreads();

        // ---- COLUMN FFT on sparse input: only rows 8..23 nonzero ----
        // Pair (p=l7):   (0, B=Ghat[16+l7])  -> u = B,  v = -B*W1
        // Pair (p=l7+8): (A=Ghat[8+l7], 0)   -> u = A,  v = A*W1*(-i)
        float cr[4], ci[4];
        {
            float2 A = sG[l7 + 8][sc];
            float2 B = sG[l7 + 16][sc];
            cr[0] = B.x;  ci[0] = B.y;
            cr[1] = A.x;  ci[1] = A.y;
            cr[2] = -fmaf(B.x, W1.x, -B.y * W1.y);
            ci[2] = -fmaf(B.x, W1.y,  B.y * W1.x);
            float p1r = fmaf(A.x, W1.x, -A.y * W1.y);
            float p1i = fmaf(A.x, W1.y,  A.y * W1.x);
            cr[3] =  p1i;
            ci[3] = -p1r;
        }
        {   // h=8 (register) with W^{2*l7}
            float t0r = cr[0] - cr[1], t0i = ci[0] - ci[1];
            cr[0] += cr[1]; ci[0] += ci[1];
            cr[1] = fmaf(t0r, W2.x, -t0i * W2.y);
            ci[1] = fmaf(t0r, W2.y,  t0i * W2.x);
            float t1r = cr[2] - cr[3], t1i = ci[2] - ci[3];
            cr[2] += cr[3]; ci[2] += ci[3];
            cr[3] = fmaf(t1r, W2.x, -t1i * W2.y);
            ci[3] = fmaf(t1r, W2.y,  t1i * W2.x);
        }
        {   // h=4 (shuffle)
            float sg = (lane & 4) ? -1.0f : 1.0f;
            #pragma unroll
            for (int m = 0; m < 4; m++) {
                float o_r = __shfl_xor_sync(0xffffffffu, cr[m], 4);
                float o_i = __shfl_xor_sync(0xffffffffu, ci[m], 4);
                float ur = fmaf(sg, cr[m], o_r);
                float ui = fmaf(sg, ci[m], o_i);
                cr[m] = fmaf(ur, W4.x, -ui * W4.y);
                ci[m] = fmaf(ur, W4.y,  ui * W4.x);
            }
        }
        {   // h=2 swap trick
            float sg = (lane & 2) ? -1.0f : 1.0f;
            bool  sw = (lane & 3) == 3;
            #pragma unroll
            for (int m = 0; m < 4; m++) {
                float o_r = __shfl_xor_sync(0xffffffffu, cr[m], 2);
                float o_i = __shfl_xor_sync(0xffffffffu, ci[m], 2);
                float ur = fmaf(sg, cr[m], o_r);
                float ui = fmaf(sg, ci[m], o_i);
                cr[m] = sw ?  ui : ur;
                ci[m] = sw ? -ur : ui;
            }
        }
        {   // h=1 identity
            float sg = (lane & 1) ? -1.0f : 1.0f;
            #pragma unroll
            for (int m = 0; m < 4; m++) {
                float o_r = __shfl_xor_sync(0xffffffffu, cr[m], 1);
                float o_i = __shfl_xor_sync(0xffffffffu, ci[m], 1);
                cr[m] = fmaf(sg, cr[m], o_r);
                ci[m] = fmaf(sg, ci[m], o_i);
            }
        }

        // ---- analytic corrections ----
        // Row-24 term: e = (cs0-1)*(-1)^{k2}; contribution e * i^{k1}, k1 mod 4 = perm[m].
        {
            float2 cs0 = sCS[0];
            float er = (cs0.x - 1.0f) * kpar;
            float ei = cs0.y * kpar;
            cr[0] += er;  ci[0] += ei;     // i^0 =  1
            cr[1] -= er;  ci[1] -= ei;     // i^2 = -1
            cr[2] -= ei;  ci[2] += er;     // i^1 =  i
            cr[3] += ei;  ci[3] -= er;     // i^3 = -i
        }
        // Constant background: 32*ones over all rows at k2=0 -> 1024 at (k1=0,k2=0).
        if (tid == 0) cr[0] += 1024.0f;

        // ---- magnitude + target + accumulate ----
        {
            float Q[4], P[4], T[4];
            #pragma unroll
            for (int m = 0; m < 4; m++) {
                Q[m] = fmaf(cr[m], cr[m], ci[m] * ci[m]);
                P[m] = sqrtf(Q[m]);
                T[m] = 0.0f;
            }
            const float* exRow = &sExT[c][0];
            #pragma unroll
            for (int s2 = 0; s2 < NS / 2; s2++) {
                float2 ex2 = *reinterpret_cast<const float2*>(&exRow[2 * s2]);
                float4 E0  = *reinterpret_cast<const float4*>(&sEy[2 * s2][rbase]);
                float4 E1  = *reinterpret_cast<const float4*>(&sEy[2 * s2 + 1][rbase]);
                T[0] = fmaf(ex2.x, E0.x, fmaf(ex2.y, E1.x, T[0]));   // r offset 0
                T[1] = fmaf(ex2.x, E0.z, fmaf(ex2.y, E1.z, T[1]));   // r offset 2
                T[2] = fmaf(ex2.x, E0.y, fmaf(ex2.y, E1.y, T[2]));   // r offset 1
                T[3] = fmaf(ex2.x, E0.w, fmaf(ex2.y, E1.w, T[3]));   // r offset 3
            }
            #pragma unroll
            for (int m = 0; m < 4; m++) {
                aP2 += Q[m];
                aT2 = fmaf(T[m], T[m], aT2);
                aPT = fmaf(P[m], T[m], aPT);
                mQ = fmaxf(mQ, Q[m]);
                mT = fmaxf(mT, T[m]);
            }
        }
        __syncthreads();   // before next batch overwrites smem
    }

    // ---- block reduction (once per NB batches) ----
    unsigned ruQ = __reduce_max_sync(0xffffffffu, (unsigned)__float_as_int(mQ));
    unsigned ruT = __reduce_max_sync(0xffffffffu, (unsigned)__float_as_int(mT));
    #pragma unroll
    for (int off = 16; off; off >>= 1) {
        aP2 += __shfl_down_sync(0xffffffffu, aP2, off);
        aT2 += __shfl_down_sync(0xffffffffu, aT2, off);
        aPT += __shfl_down_sync(0xffffffffu, aPT, off);
    }
    __shared__ int redI[16];
    if (lane == 0) {
        redD[w]      = (double)aP2;
        redD[8 + w]  = (double)aT2;
        redD[16 + w] = (double)aPT;
        redI[w]      = (int)ruQ;
        redI[8 + w]  = (int)ruT;
    }
    __syncthreads();
    if (tid == 0) {
        double bP2 = 0.0, bT2 = 0.0, bPT = 0.0;
        int    bMQ = 0, bMT = 0;
        #pragma unroll
        for (int i = 0; i < 8; i++) {
            bP2 += redD[i];
            bT2 += redD[8 + i];
            bPT += redD[16 + i];
            bMQ = max(bMQ, redI[i]);
            bMT = max(bMT, redI[8 + i]);
        }
        atomicAdd(&g_sumP2, bP2);
        atomicAdd(&g_sumT2, bT2);
        atomicAdd(&g_sumPT, bPT);
        atomicMax(&g_maxQ, bMQ);
        atomicMax(&g_maxT, bMT);

        __threadfence();
        unsigned prev = atomicAdd(&g_count, 1u);
        if (prev == gridDim.x - 1u) {
            __threadfence();
            double SP2 = g_sumP2;
            double ST2 = g_sumT2;
            double SPT = g_sumPT;
            double Mp = sqrt((double)__int_as_float(g_maxQ));
            double Mt = (double)__int_as_float(g_maxT);
            double num = SP2 / (Mp * Mp) - 2.0 * SPT / (Mp * Mt) + ST2 / (Mt * Mt);
            out[0] = (float)(num * (Mp * Mt) / sqrt(SP2 * ST2));
            // self-reset for next graph replay (matches static init state)
            g_sumP2 = 0.0;
            g_sumT2 = 0.0;
            g_sumPT = 0.0;
            g_maxQ  = 0;
            g_maxT  = 0;
            g_count = 0u;
        }
    }
}

extern "C" void kernel_launch(void* const* d_in, const int* in_sizes, int n_in,
                              void* d_out, int out_size)
{
    const float* output  = (const float*)d_in[0];
    const float* targets = (const float*)d_in[1];
    int B = in_sizes[0] / (NS * 3);

    loss_main<<<B / NB, NT>>>(output, targets, (float*)d_out);
}